// round 2
// baseline (speedup 1.0000x reference)
#include <cuda_runtime.h>
#include <cstdint>

#define B_ 4
#define C_ 192
#define S_ 64
#define L_ 512
#define SL_ (S_*L_)      // 32768
#define BN 64            // l-columns per block in vout kernel
#define KC 32            // K chunk
#define WST 194          // w_s row stride (8B-aligned rows, 2-way scatter conflicts only)

// ctx scratch: layout [b][s][c]
__device__ float g_ctx[B_*S_*C_];

// ---------- packed fp32x2 helpers (Blackwell f32x2 pipe, PTX-only) ----------
static __device__ __forceinline__ unsigned long long pk2(float x, float y) {
    unsigned long long r;
    asm("mov.b64 %0, {%1,%2};" : "=l"(r) : "r"(__float_as_uint(x)), "r"(__float_as_uint(y)));
    return r;
}
static __device__ __forceinline__ unsigned long long fma2(unsigned long long a,
                                                          unsigned long long b,
                                                          unsigned long long c) {
    unsigned long long d;
    asm("fma.rn.f32x2 %0, %1, %2, %3;" : "=l"(d) : "l"(a), "l"(b), "l"(c));
    return d;
}
static __device__ __forceinline__ float2 upk2(unsigned long long v) {
    unsigned int a, b;
    asm("mov.b64 {%0,%1}, %2;" : "=r"(a), "=r"(b) : "l"(v));
    return make_float2(__uint_as_float(a), __uint_as_float(b));
}

// ============================================================================
// Kernel 1: per (b,s): q = wq·query + bq ; softmax over L ; kctx = key·scores ;
//           ctx = wk @ kctx + bk  -> g_ctx[b][s][c]
// ============================================================================
__global__ __launch_bounds__(256) void ctx_kernel(
    const float* __restrict__ q_in, const float* __restrict__ k_in,
    const float* __restrict__ w, const float* __restrict__ bias)
{
    const int s = blockIdx.x, b = blockIdx.y;
    const int tid = threadIdx.x, lane = tid & 31, warp = tid >> 5;

    __shared__ float sc[L_];
    __shared__ float wq_s[C_];
    __shared__ float kctx_s[C_];
    __shared__ float red8[8];

    if (tid < C_) wq_s[tid] = w[tid];      // wq = row 0 of in_proj_weight
    __syncthreads();

    // ---- q projection: 2 l-positions per thread, coalesced over l ----
    const float* qb = q_in + (size_t)b*C_*SL_ + (size_t)s*L_;
    float a0 = 0.f, a1 = 0.f;
    #pragma unroll 4
    for (int c = 0; c < C_; c++) {
        const float* p = qb + (size_t)c*SL_;
        a0 = fmaf(wq_s[c], p[tid],        a0);
        a1 = fmaf(wq_s[c], p[tid + 256],  a1);
    }
    const float bq = bias[0];
    a0 += bq; a1 += bq;

    // ---- softmax over 512 (block reduce max, then sum) ----
    float m = fmaxf(a0, a1);
    #pragma unroll
    for (int o = 16; o > 0; o >>= 1) m = fmaxf(m, __shfl_xor_sync(0xffffffffu, m, o));
    if (lane == 0) red8[warp] = m;
    __syncthreads();
    float M = red8[0];
    #pragma unroll
    for (int i = 1; i < 8; i++) M = fmaxf(M, red8[i]);

    const float e0 = __expf(a0 - M), e1 = __expf(a1 - M);
    float sm = e0 + e1;
    #pragma unroll
    for (int o = 16; o > 0; o >>= 1) sm += __shfl_xor_sync(0xffffffffu, sm, o);
    __syncthreads();
    if (lane == 0) red8[warp] = sm;
    __syncthreads();
    float T = 0.f;
    #pragma unroll
    for (int i = 0; i < 8; i++) T += red8[i];
    const float inv = 1.0f / T;
    sc[tid]       = e0 * inv;
    sc[tid + 256] = e1 * inv;
    __syncthreads();

    // ---- kctx[c] = sum_l key[b,c,s,l] * scores[l] ; warp per c-stripe ----
    const float* kb = k_in + (size_t)b*C_*SL_ + (size_t)s*L_;
    for (int c = warp; c < C_; c += 8) {
        const float* p = kb + (size_t)c*SL_;
        float acc = 0.f;
        #pragma unroll 4
        for (int l = lane; l < L_; l += 32) acc = fmaf(p[l], sc[l], acc);
        #pragma unroll
        for (int o = 16; o > 0; o >>= 1) acc += __shfl_xor_sync(0xffffffffu, acc, o);
        if (lane == 0) kctx_s[c] = acc;
    }
    __syncthreads();

    // ---- ctx = wk @ kctx + bk  (wk = rows 1..C of in_proj_weight) ----
    if (tid < C_) {
        const float* wr = w + (size_t)(1 + tid) * C_;
        float acc = bias[1 + tid];
        #pragma unroll 8
        for (int c = 0; c < C_; c++) acc = fmaf(wr[c], kctx_s[c], acc);
        g_ctx[((size_t)b*S_ + s)*C_ + tid] = acc;
    }
}

// ============================================================================
// Kernel 2: per block = 64 l-columns of one (b,s):
//   tmp = relu(wv@value + bv) * ctx ;  out = wo@tmp + bo
// f32x2 register-blocked GEMM: 256 thr, per-thread 6 m-pairs x 4 j.
// ============================================================================
__device__ __forceinline__ void gemm_phase(
    const float* __restrict__ wg,   // global weight, row-major [C_][C_]
    const float* __restrict__ Bsm,  // B operand in smem, [C_][BN]
    float* __restrict__ w_s,        // smem transposed weight chunk [KC][WST]
    int tid, int tx, int ty, int m0,
    unsigned long long (&acc)[6][4])
{
    #pragma unroll
    for (int i = 0; i < 6; i++)
        #pragma unroll
        for (int j = 0; j < 4; j++) acc[i][j] = 0ull;

    // prefetch chunk 0 into registers
    float4 pf[6];
    #pragma unroll
    for (int p = 0; p < 6; p++) {
        int idx = p*256 + tid;          // 0..1535
        int kk4 = (idx & 7) << 2;       // 0,4,...,28
        int mm  = idx >> 3;             // 0..191
        pf[p] = *reinterpret_cast<const float4*>(wg + (size_t)mm*C_ + kk4);
    }

    for (int kc = 0; kc < 6; kc++) {
        __syncthreads();                // previous consumers of w_s done
        #pragma unroll
        for (int p = 0; p < 6; p++) {
            int idx = p*256 + tid;
            int kk4 = (idx & 7) << 2;
            int mm  = idx >> 3;
            w_s[(kk4+0)*WST + mm] = pf[p].x;
            w_s[(kk4+1)*WST + mm] = pf[p].y;
            w_s[(kk4+2)*WST + mm] = pf[p].z;
            w_s[(kk4+3)*WST + mm] = pf[p].w;
        }
        __syncthreads();
        if (kc < 5) {                   // prefetch next chunk (latency hidden by compute)
            #pragma unroll
            for (int p = 0; p < 6; p++) {
                int idx = p*256 + tid;
                int kk4 = (idx & 7) << 2;
                int mm  = idx >> 3;
                pf[p] = *reinterpret_cast<const float4*>(
                    wg + (size_t)mm*C_ + (kc+1)*KC + kk4);
            }
        }
        const int kbase = kc * KC;
        #pragma unroll 8
        for (int kk = 0; kk < KC; kk++) {
            // 6 m-pairs of weights, adjacent-m packed, broadcast over tx lanes
            const unsigned long long* wr =
                reinterpret_cast<const unsigned long long*>(&w_s[kk*WST + m0]);
            unsigned long long wp0 = wr[0], wp1 = wr[1], wp2 = wr[2],
                               wp3 = wr[3], wp4 = wr[4], wp5 = wr[5];
            float4 v4 = *reinterpret_cast<const float4*>(&Bsm[(kbase+kk)*BN + tx*4]);
            unsigned long long vd[4] = { pk2(v4.x, v4.x), pk2(v4.y, v4.y),
                                         pk2(v4.z, v4.z), pk2(v4.w, v4.w) };
            #pragma unroll
            for (int j = 0; j < 4; j++) {
                acc[0][j] = fma2(wp0, vd[j], acc[0][j]);
                acc[1][j] = fma2(wp1, vd[j], acc[1][j]);
                acc[2][j] = fma2(wp2, vd[j], acc[2][j]);
                acc[3][j] = fma2(wp3, vd[j], acc[3][j]);
                acc[4][j] = fma2(wp4, vd[j], acc[4][j]);
                acc[5][j] = fma2(wp5, vd[j], acc[5][j]);
            }
        }
    }
}

#define VOUT_SMEM_FLOATS (2*C_*BN + KC*WST + 3*C_)
#define VOUT_SMEM_BYTES  (VOUT_SMEM_FLOATS * 4)

__global__ __launch_bounds__(256, 1) void vout_kernel(
    const float* __restrict__ v_in,
    const float* __restrict__ w_in, const float* __restrict__ bias_in,
    const float* __restrict__ wo,   const float* __restrict__ bo,
    float* __restrict__ out)
{
    extern __shared__ float smp[];
    float* val_s = smp;                  // [C_][BN]
    float* tmp_s = smp + C_*BN;          // [C_][BN]
    float* w_s   = smp + 2*C_*BN;        // [KC][WST]
    float* ctx_s = w_s + KC*WST;         // [C_]
    float* bv_s  = ctx_s + C_;           // [C_]
    float* bo_s  = bv_s + C_;            // [C_]

    const int tid = threadIdx.x;
    const int l0  = blockIdx.x * BN;
    const int s   = blockIdx.y;
    const int b   = blockIdx.z;
    const int tx  = tid & 15;            // j-group (4 cols)
    const int ty  = tid >> 4;            // m-group (12 rows = 6 pairs)
    const int m0  = ty * 12;

    const float* wv = w_in + (size_t)(1 + C_) * C_;   // rows 193..384

    if (tid < C_) {
        ctx_s[tid] = g_ctx[((size_t)b*S_ + s)*C_ + tid];
        bv_s[tid]  = bias_in[1 + C_ + tid];
        bo_s[tid]  = bo[tid];
    }

    // load value tile [C_][BN] into smem (float4, coalesced)
    const float* vb = v_in + (size_t)b*C_*SL_ + (size_t)s*L_ + l0;
    #pragma unroll
    for (int p = 0; p < 12; p++) {
        int idx = p*256 + tid;           // 0..3071
        int c  = idx >> 4;
        int j4 = (idx & 15) << 2;
        float4 v = *reinterpret_cast<const float4*>(vb + (size_t)c*SL_ + j4);
        *reinterpret_cast<float4*>(&val_s[c*BN + j4]) = v;
    }

    unsigned long long acc[6][4];

    // ---- phase 1: v = wv @ value_tile ----
    gemm_phase(wv, val_s, w_s, tid, tx, ty, m0, acc);

    // epilogue 1: relu(v + bv) * ctx -> tmp_s
    #pragma unroll
    for (int i = 0; i < 6; i++) {
        const int m = m0 + 2*i;
        float2 r0 = upk2(acc[i][0]), r1 = upk2(acc[i][1]),
               r2 = upk2(acc[i][2]), r3 = upk2(acc[i][3]);
        const float bvl = bv_s[m],   cl = ctx_s[m];
        const float bvh = bv_s[m+1], ch = ctx_s[m+1];
        float4 lo = make_float4(fmaxf(r0.x + bvl, 0.f) * cl,
                                fmaxf(r1.x + bvl, 0.f) * cl,
                                fmaxf(r2.x + bvl, 0.f) * cl,
                                fmaxf(r3.x + bvl, 0.f) * cl);
        float4 hi = make_float4(fmaxf(r0.y + bvh, 0.f) * ch,
                                fmaxf(r1.y + bvh, 0.f) * ch,
                                fmaxf(r2.y + bvh, 0.f) * ch,
                                fmaxf(r3.y + bvh, 0.f) * ch);
        *reinterpret_cast<float4*>(&tmp_s[(m  )*BN + tx*4]) = lo;
        *reinterpret_cast<float4*>(&tmp_s[(m+1)*BN + tx*4]) = hi;
    }
    // (visibility of tmp_s is guaranteed by the two __syncthreads at the top
    //  of phase 2's first chunk, before any thread reads tmp_s)

    // ---- phase 2: out = wo @ tmp ----
    gemm_phase(wo, tmp_s, w_s, tid, tx, ty, m0, acc);

    // epilogue 2: + bo -> global
    float* ob = out + (size_t)b*C_*SL_ + (size_t)s*L_ + l0;
    #pragma unroll
    for (int i = 0; i < 6; i++) {
        const int m = m0 + 2*i;
        float2 r0 = upk2(acc[i][0]), r1 = upk2(acc[i][1]),
               r2 = upk2(acc[i][2]), r3 = upk2(acc[i][3]);
        const float bl = bo_s[m], bh = bo_s[m+1];
        float4 lo = make_float4(r0.x + bl, r1.x + bl, r2.x + bl, r3.x + bl);
        float4 hi = make_float4(r0.y + bh, r1.y + bh, r2.y + bh, r3.y + bh);
        *reinterpret_cast<float4*>(ob + (size_t)(m  )*SL_ + tx*4) = lo;
        *reinterpret_cast<float4*>(ob + (size_t)(m+1)*SL_ + tx*4) = hi;
    }
}

// ============================================================================
extern "C" void kernel_launch(void* const* d_in, const int* in_sizes, int n_in,
                              void* d_out, int out_size) {
    const float* query = (const float*)d_in[0];
    const float* key   = (const float*)d_in[1];
    const float* value = (const float*)d_in[2];
    const float* w     = (const float*)d_in[3];   // (385,192,1,1)
    const float* bias  = (const float*)d_in[4];   // (385,)
    const float* wo    = (const float*)d_in[5];   // (192,192,1,1)
    const float* bo    = (const float*)d_in[6];   // (192,)
    float* out = (float*)d_out;

    cudaFuncSetAttribute(vout_kernel,
                         cudaFuncAttributeMaxDynamicSharedMemorySize,
                         VOUT_SMEM_BYTES);

    ctx_kernel<<<dim3(S_, B_), 256>>>(query, key, w, bias);
    vout_kernel<<<dim3(L_/BN, S_, B_), 256, VOUT_SMEM_BYTES>>>(
        value, w, bias, wo, bo, out);
}

// round 4
// speedup vs baseline: 1.4047x; 1.4047x over previous
#include <cuda_runtime.h>
#include <cuda_bf16.h>
#include <cstdint>

#define B_ 4
#define C_ 192
#define S_ 64
#define L_ 512
#define SL_ (S_*L_)
#define LT_ 128

// W image: [matrix(2)][chunk(3)][hi 192x144B | lo 192x144B]
#define W_ROW    144
#define W_PART   (C_*W_ROW)          // 27648
#define W_CHUNK  (2*W_PART)          // 55296
#define W_PHASE  (3*W_CHUNK)         // 165888
__device__ float g_ctx[B_*S_*C_];
__device__ __align__(16) unsigned char g_wimg[2*W_PHASE];

// smem layout (bytes)
#define X_ROW    272
#define SM_XHI   0
#define SM_XLO   (C_*X_ROW)              // 52224
#define SM_WBUF  (2*C_*X_ROW)            // 104448
#define SM_CTX   (SM_WBUF + 2*W_CHUNK)   // 215040
#define SM_BV    (SM_CTX + 768)
#define SM_BO    (SM_BV + 768)
#define SM_TOTAL (SM_BO + 768)           // 217344

// ---------------- PTX helpers ----------------
static __device__ __forceinline__ uint32_t smem_u32(const void* p) {
    uint32_t a;
    asm("{ .reg .u64 t; cvta.to.shared.u64 t, %1; cvt.u32.u64 %0, t; }" : "=r"(a) : "l"(p));
    return a;
}
static __device__ __forceinline__ void cp16(uint32_t dst, const void* src) {
    asm volatile("cp.async.cg.shared.global [%0], [%1], 16;" :: "r"(dst), "l"(src));
}
#define CP_COMMIT() asm volatile("cp.async.commit_group;")
static __device__ __forceinline__ void ldsm4(uint32_t* r, uint32_t a) {
    asm volatile("ldmatrix.sync.aligned.m8n8.x4.shared.b16 {%0,%1,%2,%3}, [%4];"
        : "=r"(r[0]), "=r"(r[1]), "=r"(r[2]), "=r"(r[3]) : "r"(a));
}
static __device__ __forceinline__ void ldsm4t(uint32_t* r, uint32_t a) {
    asm volatile("ldmatrix.sync.aligned.m8n8.x4.trans.shared.b16 {%0,%1,%2,%3}, [%4];"
        : "=r"(r[0]), "=r"(r[1]), "=r"(r[2]), "=r"(r[3]) : "r"(a));
}
static __device__ __forceinline__ void mma16816(float* d, const uint32_t* a,
                                                const uint32_t* b) {
    asm volatile(
        "mma.sync.aligned.m16n8k16.row.col.f32.bf16.bf16.f32 "
        "{%0,%1,%2,%3}, {%4,%5,%6,%7}, {%8,%9}, {%0,%1,%2,%3};"
        : "+f"(d[0]), "+f"(d[1]), "+f"(d[2]), "+f"(d[3])
        : "r"(a[0]), "r"(a[1]), "r"(a[2]), "r"(a[3]), "r"(b[0]), "r"(b[1]));
}
static __device__ __forceinline__ uint32_t pk_bf(float x, float y) {
    __nv_bfloat162 t = __floats2bfloat162_rn(x, y);
    return *reinterpret_cast<uint32_t*>(&t);
}

// ============================================================================
__global__ void prep_weights(const float* __restrict__ w, const float* __restrict__ wo) {
    int e = blockIdx.x * 256 + threadIdx.x;
    if (e >= 2 * C_ * C_) return;
    int p = e / (C_*C_); int rem = e % (C_*C_);
    int r = rem / C_, k = rem % C_;
    float x = (p == 0) ? w[(size_t)(1 + C_ + r) * C_ + k] : wo[(size_t)r * C_ + k];
    __nv_bfloat16 h = __float2bfloat16(x);
    __nv_bfloat16 l = __float2bfloat16(x - __bfloat162float(h));
    int chunk = k >> 6, kk = k & 63;
    unsigned char* base = g_wimg + (size_t)p*W_PHASE + (size_t)chunk*W_CHUNK;
    *reinterpret_cast<unsigned short*>(base + r*W_ROW + kk*2)          = *reinterpret_cast<unsigned short*>(&h);
    *reinterpret_cast<unsigned short*>(base + W_PART + r*W_ROW + kk*2) = *reinterpret_cast<unsigned short*>(&l);
}

// ============================================================================
__global__ __launch_bounds__(512) void ctx_kernel(
    const float* __restrict__ q_in, const float* __restrict__ k_in,
    const float* __restrict__ w, const float* __restrict__ bias)
{
    const int s = blockIdx.x, b = blockIdx.y;
    const int tid = threadIdx.x, lane = tid & 31, wp = tid >> 5;

    __shared__ float sc[L_];
    __shared__ float wq_s[C_];
    __shared__ float kctx_s[C_];
    __shared__ float red[16];

    if (tid < C_) wq_s[tid] = w[tid];
    __syncthreads();

    const float* qb = q_in + (size_t)b*C_*SL_ + (size_t)s*L_;
    float a0 = 0.f, a1 = 0.f;
    #pragma unroll 8
    for (int c = 0; c < C_; c += 2) {
        a0 = fmaf(wq_s[c],   qb[(size_t)c*SL_ + tid],     a0);
        a1 = fmaf(wq_s[c+1], qb[(size_t)(c+1)*SL_ + tid], a1);
    }
    float a = a0 + a1 + bias[0];

    float m = a;
    #pragma unroll
    for (int o = 16; o > 0; o >>= 1) m = fmaxf(m, __shfl_xor_sync(~0u, m, o));
    if (lane == 0) red[wp] = m;
    __syncthreads();
    float M = red[0];
    #pragma unroll
    for (int i = 1; i < 16; i++) M = fmaxf(M, red[i]);
    __syncthreads();

    float e = __expf(a - M);
    float sm = e;
    #pragma unroll
    for (int o = 16; o > 0; o >>= 1) sm += __shfl_xor_sync(~0u, sm, o);
    if (lane == 0) red[wp] = sm;
    __syncthreads();
    float T = 0.f;
    #pragma unroll
    for (int i = 0; i < 16; i++) T += red[i];
    sc[tid] = e * (1.0f / T);
    __syncthreads();

    const float* kb = k_in + (size_t)b*C_*SL_ + (size_t)s*L_;
    for (int c = wp; c < C_; c += 16) {
        const float* p = kb + (size_t)c*SL_;
        float acc = 0.f;
        #pragma unroll
        for (int l = lane; l < L_; l += 32) acc = fmaf(p[l], sc[l], acc);
        #pragma unroll
        for (int o = 16; o > 0; o >>= 1) acc += __shfl_xor_sync(~0u, acc, o);
        if (lane == 0) kctx_s[c] = acc;
    }
    __syncthreads();

    if (tid < C_) {
        const float* wr = w + (size_t)(1 + tid) * C_;
        float acc = bias[1 + tid];
        #pragma unroll 8
        for (int c = 0; c < C_; c++) acc = fmaf(wr[c], kctx_s[c], acc);
        g_ctx[((size_t)b*S_ + s)*C_ + tid] = acc;
    }
}

// ============================================================================
// vout: per CTA = 128 l-columns of one (b,s). Both GEMMs on mma.sync bf16
// (2-term split, 3 passes). M=c_out(192), N=l(128), K=c_in(192), 3 K-chunks.
// ============================================================================
static __device__ __forceinline__ void copy_chunk(uint32_t dst, int chunk, int tid) {
    const unsigned char* src = g_wimg + (size_t)chunk * W_CHUNK;
    #pragma unroll
    for (int i = 0; i < 7; i++) {
        int off = (i*512 + tid) * 16;
        if (off < W_CHUNK) cp16(dst + off, src + off);
    }
}

__global__ __launch_bounds__(512, 1) void vout_tc(
    const float* __restrict__ v_in, const float* __restrict__ bias_in,
    const float* __restrict__ bo_g, float* __restrict__ out)
{
    extern __shared__ char sm[];
    const uint32_t smb = smem_u32(sm);
    float* ctx_s = (float*)(sm + SM_CTX);
    float* bv_s  = (float*)(sm + SM_BV);
    float* bo_s  = (float*)(sm + SM_BO);

    const int tid = threadIdx.x, lane = tid & 31, warp = tid >> 5;
    const int l0 = blockIdx.x * LT_;
    const int s  = blockIdx.y, b = blockIdx.z;
    const int m0 = (warp >> 2) * 48;     // warp M offset (c_out)
    const int n0 = (warp & 3) * 32;      // warp N offset (l)

    // kick W chunk 0 (async) before anything else
    copy_chunk(smb + SM_WBUF, 0, tid);
    CP_COMMIT();

    if (tid < C_) {
        ctx_s[tid] = g_ctx[((size_t)b*S_ + s)*C_ + tid];
        bv_s[tid]  = bias_in[1 + C_ + tid];
        bo_s[tid]  = bo_g[tid];
    }

    // ---- stage X1 = value^T (bf16 hi/lo) into smem [k=c][l], 272B rows ----
    const float* vb = v_in + (size_t)b*C_*SL_ + (size_t)s*L_ + l0;
    #pragma unroll
    for (int i = 0; i < 12; i++) {
        int idx = i*512 + tid;
        int c = idx >> 5, l4 = (idx & 31) << 2;
        float4 v = *reinterpret_cast<const float4*>(vb + (size_t)c*SL_ + l4);
        __nv_bfloat16 h0 = __float2bfloat16(v.x), h1 = __float2bfloat16(v.y),
                      h2 = __float2bfloat16(v.z), h3 = __float2bfloat16(v.w);
        float r0 = v.x - __bfloat162float(h0), r1 = v.y - __bfloat162float(h1),
              r2 = v.z - __bfloat162float(h2), r3 = v.w - __bfloat162float(h3);
        uint32_t hA, hB, lA, lB;
        { __nv_bfloat162 t = __halves2bfloat162(h0, h1); hA = *(uint32_t*)&t; }
        { __nv_bfloat162 t = __halves2bfloat162(h2, h3); hB = *(uint32_t*)&t; }
        lA = pk_bf(r0, r1); lB = pk_bf(r2, r3);
        uint32_t o = (uint32_t)c * X_ROW + (uint32_t)l4 * 2;
        asm volatile("st.shared.v2.b32 [%0], {%1,%2};" :: "r"(smb + SM_XHI + o), "r"(hA), "r"(hB));
        asm volatile("st.shared.v2.b32 [%0], {%1,%2};" :: "r"(smb + SM_XLO + o), "r"(lA), "r"(lB));
    }
    __syncthreads();

    float acc[3][4][4];
    #pragma unroll
    for (int i = 0; i < 3; i++)
        #pragma unroll
        for (int j = 0; j < 4; j++)
            #pragma unroll
            for (int q = 0; q < 4; q++) acc[i][j][q] = 0.f;

    float* ob = out + (size_t)b*C_*SL_ + (size_t)s*L_ + l0;

    for (int c = 0; c < 6; c++) {
        if (c < 5) { copy_chunk(smb + SM_WBUF + ((c+1)&1)*W_CHUNK, c+1, tid); CP_COMMIT(); }
        if (c < 5) asm volatile("cp.async.wait_group 1;");
        else       asm volatile("cp.async.wait_group 0;");
        __syncthreads();

        const uint32_t wb = smb + SM_WBUF + (c&1)*W_CHUNK;
        const int kb = (c % 3) * 64;

        #pragma unroll
        for (int ks = 0; ks < 4; ks++) {
            const int kg = kb + ks*16;
            uint32_t Ah[3][4], Al[3][4], Xh[4][2], Xl[4][2];
            #pragma unroll
            for (int mt = 0; mt < 3; mt++) {
                uint32_t a = wb + (uint32_t)(m0 + mt*16 + (lane & 15))*W_ROW
                           + (uint32_t)ks*32 + (uint32_t)(lane >> 4)*16;
                ldsm4(Ah[mt], a);
                ldsm4(Al[mt], a + W_PART);
            }
            #pragma unroll
            for (int h = 0; h < 2; h++) {
                uint32_t xo = (uint32_t)(kg + (lane & 15))*X_ROW
                            + (uint32_t)(n0 + h*16 + 8*(lane >> 4))*2;
                uint32_t r[4];
                ldsm4t(r, smb + SM_XHI + xo);
                Xh[2*h][0] = r[0]; Xh[2*h][1] = r[1];
                Xh[2*h+1][0] = r[2]; Xh[2*h+1][1] = r[3];
                ldsm4t(r, smb + SM_XLO + xo);
                Xl[2*h][0] = r[0]; Xl[2*h][1] = r[1];
                Xl[2*h+1][0] = r[2]; Xl[2*h+1][1] = r[3];
            }
            #pragma unroll
            for (int mt = 0; mt < 3; mt++)
                #pragma unroll
                for (int nt = 0; nt < 4; nt++) {
                    mma16816(acc[mt][nt], Ah[mt], Xh[nt]);
                    mma16816(acc[mt][nt], Ah[mt], Xl[nt]);
                    mma16816(acc[mt][nt], Al[mt], Xh[nt]);
                }
        }

        if (c == 2) {
            // ---- epilogue 1: relu(D1+bv)*ctx -> split -> X buffers ----
            __syncthreads();   // all warps done reading X1
            #pragma unroll
            for (int mt = 0; mt < 3; mt++) {
                const int r0 = m0 + mt*16 + (lane >> 2);
                const float bva = bv_s[r0],   cta = ctx_s[r0];
                const float bvb = bv_s[r0+8], ctb = ctx_s[r0+8];
                #pragma unroll
                for (int nt = 0; nt < 4; nt++) {
                    const int col = n0 + nt*8 + (lane & 3)*2;
                    float v0 = fmaxf(acc[mt][nt][0] + bva, 0.f) * cta;
                    float v1 = fmaxf(acc[mt][nt][1] + bva, 0.f) * cta;
                    float v2 = fmaxf(acc[mt][nt][2] + bvb, 0.f) * ctb;
                    float v3 = fmaxf(acc[mt][nt][3] + bvb, 0.f) * ctb;
                    __nv_bfloat16 h0 = __float2bfloat16(v0), h1 = __float2bfloat16(v1),
                                  h2 = __float2bfloat16(v2), h3 = __float2bfloat16(v3);
                    uint32_t hA, hB;
                    { __nv_bfloat162 t = __halves2bfloat162(h0, h1); hA = *(uint32_t*)&t; }
                    { __nv_bfloat162 t = __halves2bfloat162(h2, h3); hB = *(uint32_t*)&t; }
                    uint32_t lA = pk_bf(v0 - __bfloat162float(h0), v1 - __bfloat162float(h1));
                    uint32_t lB = pk_bf(v2 - __bfloat162float(h2), v3 - __bfloat162float(h3));
                    uint32_t oA = (uint32_t)r0*X_ROW + (uint32_t)col*2;
                    uint32_t oB = (uint32_t)(r0+8)*X_ROW + (uint32_t)col*2;
                    asm volatile("st.shared.b32 [%0], %1;" :: "r"(smb + SM_XHI + oA), "r"(hA));
                    asm volatile("st.shared.b32 [%0], %1;" :: "r"(smb + SM_XHI + oB), "r"(hB));
                    asm volatile("st.shared.b32 [%0], %1;" :: "r"(smb + SM_XLO + oA), "r"(lA));
                    asm volatile("st.shared.b32 [%0], %1;" :: "r"(smb + SM_XLO + oB), "r"(lB));
                    acc[mt][nt][0] = acc[mt][nt][1] = acc[mt][nt][2] = acc[mt][nt][3] = 0.f;
                }
            }
        }
        __syncthreads();
    }

    // ---- writeout: D2 + bo ----
    #pragma unroll
    for (int mt = 0; mt < 3; mt++) {
        const int r0 = m0 + mt*16 + (lane >> 2);
        const float ba = bo_s[r0], bb = bo_s[r0+8];
        #pragma unroll
        for (int nt = 0; nt < 4; nt++) {
            const int col = n0 + nt*8 + (lane & 3)*2;
            float2 lo = make_float2(acc[mt][nt][0] + ba, acc[mt][nt][1] + ba);
            float2 hi = make_float2(acc[mt][nt][2] + bb, acc[mt][nt][3] + bb);
            *reinterpret_cast<float2*>(ob + (size_t)r0*SL_ + col)     = lo;
            *reinterpret_cast<float2*>(ob + (size_t)(r0+8)*SL_ + col) = hi;
        }
    }
}

// ============================================================================
extern "C" void kernel_launch(void* const* d_in, const int* in_sizes, int n_in,
                              void* d_out, int out_size) {
    const float* query = (const float*)d_in[0];
    const float* key   = (const float*)d_in[1];
    const float* value = (const float*)d_in[2];
    const float* w     = (const float*)d_in[3];
    const float* bias  = (const float*)d_in[4];
    const float* wo    = (const float*)d_in[5];
    const float* bo    = (const float*)d_in[6];
    float* out = (float*)d_out;

    cudaFuncSetAttribute(vout_tc,
                         cudaFuncAttributeMaxDynamicSharedMemorySize, SM_TOTAL);

    prep_weights<<<(2*C_*C_ + 255)/256, 256>>>(w, wo);
    ctx_kernel<<<dim3(S_, B_), 512>>>(query, key, w, bias);
    vout_tc<<<dim3(L_/LT_, S_, B_), 512, SM_TOTAL>>>(value, bias, bo, out);
}